// round 2
// baseline (speedup 1.0000x reference)
#include <cuda_runtime.h>
#include <math.h>

#define NQ   50000
#define KK   48
#define CC   128
#define HH   8
#define DD   16
#define FF_  256
#define OUTC 128

// Scratch (device globals: allocation-guard-safe)
__device__ float g_QW[(size_t)NQ * 1024];   // [n][h][c]  = sum_d q[hd]*wk[hd][c]
__device__ float g_QB[(size_t)NQ * 8];      // [n][h]     = sum_d q[hd]*bk[hd]
__device__ float g_mix[(size_t)NQ * 1024];  // [n][h][c]  = sum_k attn[h,k]*kf[k,c]

// ---------------------------------------------------------------------------
// Kernel 1: Q = vf @ wq^T + bq, then QW[n,h,c] = sum_d Q[hd]*wk[hd,c], QB.
// 64 queries per 256-thread block. dynamic smem = 64KB (xs + qs tiles).
// ---------------------------------------------------------------------------
__global__ __launch_bounds__(256) void k_qw(const float* __restrict__ vf,
                                            const float* __restrict__ ipw,
                                            const float* __restrict__ ipb) {
    extern __shared__ float sm[];
    float* xs = sm;            // 64*128
    float* qs = sm + 64 * 128; // 64*128
    int q0 = blockIdx.x * 64;
    int tid = threadIdx.x;

    for (int i = tid; i < 64 * 128; i += 256) {
        int qq = i >> 7;
        xs[i] = (q0 + qq < NQ) ? vf[(size_t)(q0 + qq) * CC + (i & 127)] : 0.f;
    }
    __syncthreads();

    int o = tid & 127, g = tid >> 7;
    // ---- Q ----
    {
        float acc[32];
#pragma unroll
        for (int j = 0; j < 32; j++) acc[j] = 0.f;
        const float* wq = ipw + (size_t)o * CC;  // wq rows 0..127
        for (int cc = 0; cc < CC; cc += 4) {
            float4 w4 = *(const float4*)(wq + cc);
#pragma unroll
            for (int j = 0; j < 32; j++) {
                float4 x4 = *(const float4*)(xs + (g * 32 + j) * CC + cc);
                acc[j] += w4.x * x4.x + w4.y * x4.y + w4.z * x4.z + w4.w * x4.w;
            }
        }
        float b = ipb[o];
#pragma unroll
        for (int j = 0; j < 32; j++) qs[(g * 32 + j) * CC + o] = acc[j] + b;
    }
    __syncthreads();

    // ---- QW ----
    {
        const int c = o;
        for (int h = 0; h < HH; h++) {
            float wreg[16];
#pragma unroll
            for (int d = 0; d < 16; d++)
                wreg[d] = ipw[(size_t)(CC + h * 16 + d) * CC + c];  // wk rows 128..255
            for (int j = 0; j < 32; j++) {
                int qq = g * 32 + j;
                float a = 0.f;
#pragma unroll
                for (int d4 = 0; d4 < 16; d4 += 4) {
                    float4 q4 = *(const float4*)(qs + qq * CC + h * 16 + d4);
                    a += q4.x * wreg[d4] + q4.y * wreg[d4 + 1] +
                         q4.z * wreg[d4 + 2] + q4.w * wreg[d4 + 3];
                }
                if (q0 + qq < NQ) g_QW[(size_t)(q0 + qq) * 1024 + h * 128 + c] = a;
            }
        }
    }
    // ---- QB ----
    for (int i = tid; i < 64 * 8; i += 256) {
        int qq = i >> 3, h = i & 7;
        if (q0 + qq < NQ) {
            float a = 0.f;
#pragma unroll
            for (int d = 0; d < 16; d++)
                a += qs[qq * CC + h * 16 + d] * ipb[CC + h * 16 + d];
            g_QB[(size_t)(q0 + qq) * 8 + h] = a;
        }
    }
}

// ---------------------------------------------------------------------------
// Kernel 2: per-query attention (gather + pos_emb + scores + softmax + mix).
// 1 query per 128-thread block. Static smem ~26KB.
// ---------------------------------------------------------------------------
__global__ __launch_bounds__(128) void k_attn(const float* __restrict__ vf,
                                              const float* __restrict__ coords,
                                              const int* __restrict__ kidx,
                                              const int* __restrict__ kmask,
                                              const float* __restrict__ kpw,
                                              const float* __restrict__ kpb) {
    __shared__ float kf[KK][CC];
    __shared__ float s_sc[HH][KK];
    __shared__ int s_idx[KK];
    __shared__ int s_msk[KK];
    __shared__ float s_rel[KK][4];
    __shared__ float s_qc[3];

    int n = blockIdx.x;
    int tid = threadIdx.x;
    if (tid < 3) s_qc[tid] = coords[(size_t)n * 3 + tid];
    if (tid < KK) {
        s_idx[tid] = kidx[(size_t)n * KK + tid];
        s_msk[tid] = kmask[(size_t)n * KK + tid];
    }
    __syncthreads();
    if (tid < KK) {
        int id = s_idx[tid];
        s_rel[tid][0] = coords[(size_t)id * 3 + 0] - s_qc[0];
        s_rel[tid][1] = coords[(size_t)id * 3 + 1] - s_qc[1];
        s_rel[tid][2] = coords[(size_t)id * 3 + 2] - s_qc[2];
    }
    float w0 = kpw[tid * 3 + 0], w1 = kpw[tid * 3 + 1], w2 = kpw[tid * 3 + 2];
    float pb = kpb[tid];
    __syncthreads();

    // gather + pos_emb
#pragma unroll 4
    for (int k = 0; k < KK; k++) {
        float pe = s_rel[k][0] * w0 + s_rel[k][1] * w1 + s_rel[k][2] * w2 + pb;
        pe = fmaxf(pe, 0.f);
        kf[k][tid] = vf[(size_t)s_idx[k] * CC + tid] + pe;
    }

    int lane = tid & 31, wp = tid >> 5;
    const float* qwb = g_QW + (size_t)n * 1024;
    float4 qw4[8];
    float qbv[8];
#pragma unroll
    for (int h = 0; h < 8; h++) {
        qw4[h] = *(const float4*)(qwb + h * 128 + lane * 4);
        qbv[h] = g_QB[(size_t)n * 8 + h];
    }
    __syncthreads();

    // scores: warp wp handles keys wp, wp+4, ...
    for (int k = wp; k < KK; k += 4) {
        float4 k4 = *(const float4*)(&kf[k][lane * 4]);
        float p[8];
#pragma unroll
        for (int h = 0; h < 8; h++)
            p[h] = k4.x * qw4[h].x + k4.y * qw4[h].y + k4.z * qw4[h].z + k4.w * qw4[h].w;
#pragma unroll
        for (int h = 0; h < 8; h++) {
            float v = p[h];
            v += __shfl_down_sync(0xffffffffu, v, 16);
            v += __shfl_down_sync(0xffffffffu, v, 8);
            v += __shfl_down_sync(0xffffffffu, v, 4);
            v += __shfl_down_sync(0xffffffffu, v, 2);
            v += __shfl_down_sync(0xffffffffu, v, 1);
            if (lane == 0) s_sc[h][k] = (v + qbv[h]) * 0.25f;  // 1/sqrt(16)
        }
    }
    __syncthreads();

    // mask + softmax: warp wp handles heads wp and wp+4
    for (int h = wp; h < HH; h += 4) {
        float a = s_sc[h][lane];
        if (s_msk[lane]) a = -1e9f;
        float bsc = -INFINITY;
        if (lane < 16) {
            bsc = s_sc[h][32 + lane];
            if (s_msk[32 + lane]) bsc = -1e9f;
        }
        float m = fmaxf(a, bsc);
#pragma unroll
        for (int off = 16; off; off >>= 1) m = fmaxf(m, __shfl_xor_sync(0xffffffffu, m, off));
        float ea = expf(a - m);
        float eb = (lane < 16) ? expf(bsc - m) : 0.f;
        float s = ea + eb;
#pragma unroll
        for (int off = 16; off; off >>= 1) s += __shfl_xor_sync(0xffffffffu, s, off);
        float inv = 1.f / s;
        s_sc[h][lane] = ea * inv;
        if (lane < 16) s_sc[h][32 + lane] = eb * inv;
    }
    __syncthreads();

    // mix[h][c] = sum_k attn[h,k]*kf[k,c]; warp wp -> heads 2wp, 2wp+1
    int h0 = 2 * wp, h1 = h0 + 1;
    float4 a0 = make_float4(0, 0, 0, 0), a1 = make_float4(0, 0, 0, 0);
#pragma unroll 4
    for (int k = 0; k < KK; k++) {
        float4 k4 = *(const float4*)(&kf[k][lane * 4]);
        float t0 = s_sc[h0][k], t1 = s_sc[h1][k];
        a0.x += k4.x * t0; a0.y += k4.y * t0; a0.z += k4.z * t0; a0.w += k4.w * t0;
        a1.x += k4.x * t1; a1.y += k4.y * t1; a1.z += k4.z * t1; a1.w += k4.w * t1;
    }
    float* mo = g_mix + (size_t)n * 1024;
    *(float4*)(mo + h0 * 128 + lane * 4) = a0;
    *(float4*)(mo + h1 * 128 + lane * 4) = a1;
}

// ---------------------------------------------------------------------------
// LayerNorm over 128 channels for a 32-query smem tile; one warp per query.
// ---------------------------------------------------------------------------
__device__ __forceinline__ void ln_norm(float* buf, const float* __restrict__ gg,
                                        const float* __restrict__ bb, int lane, int wid) {
    for (int qq = wid; qq < 32; qq += 8) {
        float4 v = *(const float4*)(buf + qq * CC + lane * 4);
        float s = v.x + v.y + v.z + v.w;
        float s2 = v.x * v.x + v.y * v.y + v.z * v.z + v.w * v.w;
#pragma unroll
        for (int off = 16; off; off >>= 1) {
            s += __shfl_xor_sync(0xffffffffu, s, off);
            s2 += __shfl_xor_sync(0xffffffffu, s2, off);
        }
        float mean = s * (1.f / 128.f);
        float var = s2 * (1.f / 128.f) - mean * mean;
        float inv = rsqrtf(var + 1e-5f);
        float4 g4 = *(const float4*)(gg + lane * 4);
        float4 b4 = *(const float4*)(bb + lane * 4);
        v.x = (v.x - mean) * inv * g4.x + b4.x;
        v.y = (v.y - mean) * inv * g4.y + b4.y;
        v.z = (v.z - mean) * inv * g4.z + b4.z;
        v.w = (v.w - mean) * inv * g4.w + b4.w;
        *(float4*)(buf + qq * CC + lane * 4) = v;
    }
}

// ---------------------------------------------------------------------------
// Kernel 3: dense tail. ctx -> out_proj -> +res LN1 -> FFN -> +res LN2 ->
// head -> LN3 -> relu. 32 queries per 256-thread block, dyn smem 80KB.
// ---------------------------------------------------------------------------
__global__ __launch_bounds__(256) void k_tail(
    const float* __restrict__ vf, const float* __restrict__ ipw,
    const float* __restrict__ ipb, const float* __restrict__ wo,
    const float* __restrict__ bo, const float* __restrict__ ln1g,
    const float* __restrict__ ln1b, const float* __restrict__ ln2g,
    const float* __restrict__ ln2b, const float* __restrict__ f1w,
    const float* __restrict__ f1b, const float* __restrict__ f2w,
    const float* __restrict__ f2b, const float* __restrict__ outw,
    const float* __restrict__ outb, const float* __restrict__ ln3g,
    const float* __restrict__ ln3b, float* __restrict__ out) {
    extern __shared__ float sm[];
    float* s_a = sm;           // 32*128: mix tile, later pre-LN3 out
    float* s_c = sm + 4096;    // 32*128: ctx, later x2
    float* s_x = sm + 8192;    // 32*128: x1
    float* s_h = sm + 12288;   // 32*256: hidden
    int q0 = blockIdx.x * 32;
    int tid = threadIdx.x;
    int lane = tid & 31, wid = tid >> 5;

    // ---- ctx[qq][h*16+d] = sum_c mix[qq][h][c]*wv[h16+d][c] + bv ----
    {
        int dq = tid & 15, r = tid >> 4;  // r in 0..15
        for (int h = 0; h < HH; h++) {
            __syncthreads();
            for (int i = tid; i < 32 * 128; i += 256) {
                int qq = i >> 7;
                s_a[i] = (q0 + qq < NQ)
                             ? g_mix[(size_t)(q0 + qq) * 1024 + h * 128 + (i & 127)]
                             : 0.f;
            }
            __syncthreads();
            int o = h * 16 + dq;
            const float* wv = ipw + (size_t)(2 * CC + o) * CC;  // wv rows 256..383
            float a0 = 0.f, a1 = 0.f;
            for (int cc = 0; cc < CC; cc += 4) {
                float4 w4 = *(const float4*)(wv + cc);
                float4 m0 = *(const float4*)(s_a + r * CC + cc);
                float4 m1 = *(const float4*)(s_a + (r + 16) * CC + cc);
                a0 += w4.x * m0.x + w4.y * m0.y + w4.z * m0.z + w4.w * m0.w;
                a1 += w4.x * m1.x + w4.y * m1.y + w4.z * m1.z + w4.w * m1.w;
            }
            float bb = ipb[2 * CC + o];
            s_c[r * CC + o] = a0 + bb;
            s_c[(r + 16) * CC + o] = a1 + bb;
        }
        __syncthreads();
    }

    // ---- attend = ctx @ wo^T + bo ; x1 = vf + attend ----
    {
        int c = tid & 127, g = tid >> 7;
        float acc[16];
#pragma unroll
        for (int j = 0; j < 16; j++) acc[j] = 0.f;
        const float* wrow = wo + (size_t)c * CC;
        for (int cc = 0; cc < CC; cc += 4) {
            float4 w4 = *(const float4*)(wrow + cc);
#pragma unroll
            for (int j = 0; j < 16; j++) {
                float4 x4 = *(const float4*)(s_c + (g * 16 + j) * CC + cc);
                acc[j] += w4.x * x4.x + w4.y * x4.y + w4.z * x4.z + w4.w * x4.w;
            }
        }
        float bb = bo[c];
#pragma unroll
        for (int j = 0; j < 16; j++) {
            int qq = g * 16 + j;
            float vfv = (q0 + qq < NQ) ? vf[(size_t)(q0 + qq) * CC + c] : 0.f;
            s_x[qq * CC + c] = vfv + acc[j] + bb;
        }
        __syncthreads();
    }
    ln_norm(s_x, ln1g, ln1b, lane, wid);
    __syncthreads();

    // ---- hidden = relu(x1 @ ff1^T + b1) ----
    {
        int f = tid;
        float acc[32];
#pragma unroll
        for (int j = 0; j < 32; j++) acc[j] = 0.f;
        const float* wrow = f1w + (size_t)f * CC;
        for (int cc = 0; cc < CC; cc += 4) {
            float4 w4 = *(const float4*)(wrow + cc);
#pragma unroll
            for (int j = 0; j < 32; j++) {
                float4 x4 = *(const float4*)(s_x + j * CC + cc);
                acc[j] += w4.x * x4.x + w4.y * x4.y + w4.z * x4.z + w4.w * x4.w;
            }
        }
        float bb = f1b[f];
#pragma unroll
        for (int j = 0; j < 32; j++) s_h[j * FF_ + f] = fmaxf(acc[j] + bb, 0.f);
        __syncthreads();
    }

    // ---- y = hidden @ ff2^T + b2 ; x2 = x1 + y ----
    {
        int c = tid & 127, g = tid >> 7;
        float acc[16];
#pragma unroll
        for (int j = 0; j < 16; j++) acc[j] = 0.f;
        const float* wrow = f2w + (size_t)c * FF_;
        for (int ff = 0; ff < FF_; ff += 4) {
            float4 w4 = *(const float4*)(wrow + ff);
#pragma unroll
            for (int j = 0; j < 16; j++) {
                float4 h4 = *(const float4*)(s_h + (g * 16 + j) * FF_ + ff);
                acc[j] += w4.x * h4.x + w4.y * h4.y + w4.z * h4.z + w4.w * h4.w;
            }
        }
        float bb = f2b[c];
#pragma unroll
        for (int j = 0; j < 16; j++) {
            int qq = g * 16 + j;
            s_c[qq * CC + c] = s_x[qq * CC + c] + acc[j] + bb;
        }
        __syncthreads();
    }
    ln_norm(s_c, ln2g, ln2b, lane, wid);
    __syncthreads();

    // ---- o = x2 @ outw^T + outb ----
    {
        int o = tid & 127, g = tid >> 7;
        float acc[16];
#pragma unroll
        for (int j = 0; j < 16; j++) acc[j] = 0.f;
        const float* wrow = outw + (size_t)o * CC;
        for (int cc = 0; cc < CC; cc += 4) {
            float4 w4 = *(const float4*)(wrow + cc);
#pragma unroll
            for (int j = 0; j < 16; j++) {
                float4 x4 = *(const float4*)(s_c + (g * 16 + j) * CC + cc);
                acc[j] += w4.x * x4.x + w4.y * x4.y + w4.z * x4.z + w4.w * x4.w;
            }
        }
        float bb = outb[o];
#pragma unroll
        for (int j = 0; j < 16; j++) s_a[(g * 16 + j) * CC + o] = acc[j] + bb;
        __syncthreads();
    }

    // ---- LN3 + relu + store ----
    for (int qq = wid; qq < 32; qq += 8) {
        if (q0 + qq >= NQ) continue;
        float4 v = *(const float4*)(s_a + qq * CC + lane * 4);
        float s = v.x + v.y + v.z + v.w;
        float s2 = v.x * v.x + v.y * v.y + v.z * v.z + v.w * v.w;
#pragma unroll
        for (int off = 16; off; off >>= 1) {
            s += __shfl_xor_sync(0xffffffffu, s, off);
            s2 += __shfl_xor_sync(0xffffffffu, s2, off);
        }
        float mean = s * (1.f / 128.f);
        float var = s2 * (1.f / 128.f) - mean * mean;
        float inv = rsqrtf(var + 1e-5f);
        float4 g4 = *(const float4*)(ln3g + lane * 4);
        float4 b4 = *(const float4*)(ln3b + lane * 4);
        v.x = fmaxf((v.x - mean) * inv * g4.x + b4.x, 0.f);
        v.y = fmaxf((v.y - mean) * inv * g4.y + b4.y, 0.f);
        v.z = fmaxf((v.z - mean) * inv * g4.z + b4.z, 0.f);
        v.w = fmaxf((v.w - mean) * inv * g4.w + b4.w, 0.f);
        *(float4*)(out + (size_t)(q0 + qq) * OUTC + lane * 4) = v;
    }
}

// ---------------------------------------------------------------------------
extern "C" void kernel_launch(void* const* d_in, const int* in_sizes, int n_in,
                              void* d_out, int out_size) {
    const float* vf = (const float*)d_in[0];
    const float* coords = (const float*)d_in[1];
    const int* kidx = (const int*)d_in[2];
    const int* kmask = (const int*)d_in[3];
    const float* ipw = (const float*)d_in[4];
    const float* ipb = (const float*)d_in[5];
    const float* wo = (const float*)d_in[6];
    const float* bo = (const float*)d_in[7];
    const float* kpw = (const float*)d_in[8];
    const float* kpb = (const float*)d_in[9];
    const float* ln1g = (const float*)d_in[10];
    const float* ln1b = (const float*)d_in[11];
    const float* ln2g = (const float*)d_in[12];
    const float* ln2b = (const float*)d_in[13];
    const float* f1w = (const float*)d_in[14];
    const float* f1b = (const float*)d_in[15];
    const float* f2w = (const float*)d_in[16];
    const float* f2b = (const float*)d_in[17];
    const float* outw = (const float*)d_in[18];
    const float* outb = (const float*)d_in[19];
    const float* ln3g = (const float*)d_in[20];
    const float* ln3b = (const float*)d_in[21];
    float* out = (float*)d_out;

    cudaFuncSetAttribute(k_qw, cudaFuncAttributeMaxDynamicSharedMemorySize, 65536);
    cudaFuncSetAttribute(k_tail, cudaFuncAttributeMaxDynamicSharedMemorySize, 81920);

    k_qw<<<(NQ + 63) / 64, 256, 65536>>>(vf, ipw, ipb);
    k_attn<<<NQ, 128>>>(vf, coords, kidx, kmask, kpw, kpb);
    k_tail<<<(NQ + 31) / 32, 256, 81920>>>(vf, ipw, ipb, wo, bo, ln1g, ln1b,
                                           ln2g, ln2b, f1w, f1b, f2w, f2b,
                                           outw, outb, ln3g, ln3b, out);
}